// round 3
// baseline (speedup 1.0000x reference)
#include <cuda_runtime.h>
#include <math.h>
#include <stdint.h>

#define N_NODES 50000
#define N_EDGES 800000
#define DIM 128

// ---------------- scratch (static device globals; no allocation) ----------------
__device__ int   g_is64;
__device__ int   g_cnt[N_NODES];
__device__ float g_dinv[N_NODES];
__device__ int   g_offs[N_NODES + 1];
__device__ int   g_cursor[N_NODES];
__device__ int   g_src[N_EDGES];
__device__ float g_w[N_EDGES];
__device__ float g_bufA[(size_t)N_NODES * DIM];
__device__ float g_bufB[(size_t)N_NODES * DIM];
// transposed + tf32-split weights: Wt[k][n], hi/lo parts
__device__ float g_WtHi0[DIM * DIM], g_WtLo0[DIM * DIM];
__device__ float g_WtHi1[DIM * DIM], g_WtLo1[DIM * DIM];
__device__ float g_WtHi2[DIM * 64],  g_WtLo2[DIM * 64];

// ---------------- tf32 helpers ----------------
__device__ __forceinline__ float tf32_round(float f) {
    uint32_t u;
    asm("cvt.rna.tf32.f32 %0, %1;" : "=r"(u) : "f"(f));
    return __uint_as_float(u);
}
__device__ __forceinline__ void tf32_split(float f, float& hi, float& lo) {
    hi = tf32_round(f);
    lo = tf32_round(f - hi);
}
__device__ __forceinline__ void mma_tf32(float* c, const uint32_t* a, uint32_t b0, uint32_t b1) {
    asm volatile(
        "mma.sync.aligned.m16n8k8.row.col.f32.tf32.tf32.f32 "
        "{%0,%1,%2,%3}, {%4,%5,%6,%7}, {%8,%9}, {%0,%1,%2,%3};"
        : "+f"(c[0]), "+f"(c[1]), "+f"(c[2]), "+f"(c[3])
        : "r"(a[0]), "r"(a[1]), "r"(a[2]), "r"(a[3]), "r"(b0), "r"(b1));
}

// ---------------- preprocessing ----------------
// zero counters; block 0 also detects edge-index dtype.
// int64 layout viewed as int32 has all odd words == 0 (node ids < 2^31).
__global__ void zero_detect_kernel(const int* __restrict__ w) {
    int i = blockIdx.x * blockDim.x + threadIdx.x;
    if (i < N_NODES) g_cnt[i] = 0;
    if (blockIdx.x == 0) {
        __shared__ int nz;
        if (threadIdx.x == 0) nz = 0;
        __syncthreads();
        if (w[2 * threadIdx.x + 1] != 0) atomicOr(&nz, 1);
        __syncthreads();
        if (threadIdx.x == 0) g_is64 = (nz == 0) ? 1 : 0;
    }
}

__device__ __forceinline__ int load_idx(const void* ei, int pos) {
    return g_is64 ? (int)((const long long*)ei)[pos] : ((const int*)ei)[pos];
}

__global__ void hist_kernel(const void* __restrict__ ei, int E) {
    int i = blockIdx.x * blockDim.x + threadIdx.x;
    if (i < E) {
        int c = load_idx(ei, E + i);   // col = second row of [2, E]
        if ((unsigned)c < N_NODES) atomicAdd(&g_cnt[c], 1);
    }
}

// Single-block exclusive scan over g_cnt -> g_offs / g_cursor; also computes dinv.
__global__ void scan_kernel(int n) {
    __shared__ int wsum[32];
    __shared__ int s_carry;
    int tid = threadIdx.x, lane = tid & 31, wid = tid >> 5;
    if (tid == 0) s_carry = 0;
    __syncthreads();
    for (int base = 0; base < n; base += 1024) {
        int i = base + tid;
        int v = (i < n) ? g_cnt[i] : 0;
        if (i < n) g_dinv[i] = rsqrtf((float)(v + 1));   // deg incl. self-loop
        int x = v;
        #pragma unroll
        for (int d = 1; d < 32; d <<= 1) {
            int t = __shfl_up_sync(0xffffffffu, x, d);
            if (lane >= d) x += t;
        }
        if (lane == 31) wsum[wid] = x;
        __syncthreads();
        if (tid < 32) {
            int s = wsum[tid];
            #pragma unroll
            for (int d = 1; d < 32; d <<= 1) {
                int t = __shfl_up_sync(0xffffffffu, s, d);
                if (tid >= d) s += t;
            }
            wsum[tid] = s;
        }
        __syncthreads();
        int carry = s_carry;
        int wpre = (wid == 0) ? 0 : wsum[wid - 1];
        int excl = carry + wpre + (x - v);
        if (i < n) { g_offs[i] = excl; g_cursor[i] = excl; }
        int total = wsum[31];
        __syncthreads();
        if (tid == 0) s_carry = carry + total;
        __syncthreads();
    }
    if (tid == 0) g_offs[n] = s_carry;
}

__global__ void scatter_kernel(const void* __restrict__ ei, int E) {
    int i = blockIdx.x * blockDim.x + threadIdx.x;
    if (i < E) {
        int r = load_idx(ei, i);
        int c = load_idx(ei, E + i);
        if ((unsigned)r < N_NODES && (unsigned)c < N_NODES) {
            int pos = atomicAdd(&g_cursor[c], 1);
            if ((unsigned)pos < N_EDGES) {
                g_src[pos] = r;
                g_w[pos] = g_dinv[r] * g_dinv[c];
            }
        }
    }
}

// Transpose + tf32-split all three weight matrices in one launch.
__global__ void prep_weights_kernel(const float* __restrict__ W0,
                                    const float* __restrict__ W1,
                                    const float* __restrict__ W2) {
    int idx = blockIdx.x * blockDim.x + threadIdx.x;
    const float* W; float *Hi, *Lo; int dout, off;
    if (idx < 16384)       { W = W0; Hi = g_WtHi0; Lo = g_WtLo0; dout = 128; off = idx; }
    else if (idx < 32768)  { W = W1; Hi = g_WtHi1; Lo = g_WtLo1; dout = 128; off = idx - 16384; }
    else if (idx < 40960)  { W = W2; Hi = g_WtHi2; Lo = g_WtLo2; dout = 64;  off = idx - 32768; }
    else return;
    int n = off / 128, k = off % 128;   // W is [dout][128]
    float h, l;
    tf32_split(W[off], h, l);
    Hi[k * dout + n] = h;
    Lo[k * dout + n] = l;
}

// ---------------- split-TF32 tensor-core GEMM ----------------
// g_bufA[N,DOUT] = X[N,128] @ Wt[128,DOUT], 3xTF32 (error ~1e-6).
// Block: 256 threads (8 warps = 2 m-groups x 4 n-groups), BM=64 rows.
template <int DOUT>
__global__ void gemm_tf32_kernel(const float* __restrict__ Xext, int src_global, int wsel,
                                 int nrows) {
    constexpr int BM = 64;
    constexpr int LDX = 132;           // %32 == 4 -> A-frag LDS conflict-free
    constexpr int LDW = DOUT + 8;      // %32 == 8 -> B-frag LDS conflict-free
    constexpr int NT = DOUT / 32;      // 8-wide n-tiles per warp (warp covers DOUT/4 cols)
    const float* X = src_global ? g_bufB : Xext;
    const float* WtHi = (wsel == 0) ? g_WtHi0 : (wsel == 1) ? g_WtHi1 : g_WtHi2;
    const float* WtLo = (wsel == 0) ? g_WtLo0 : (wsel == 1) ? g_WtLo1 : g_WtLo2;

    extern __shared__ float sm[];
    float* XsHi = sm;
    float* XsLo = XsHi + BM * LDX;
    float* WsHi = XsLo + BM * LDX;
    float* WsLo = WsHi + DIM * LDW;

    int tid = threadIdx.x;
    int row_base = blockIdx.x * BM;

    // stage weights (already tf32-split in gmem)
    for (int idx = tid; idx < DIM * DOUT / 4; idx += 256) {
        int k = idx / (DOUT / 4), c4 = idx % (DOUT / 4);
        float4 h = ((const float4*)(WtHi + k * DOUT))[c4];
        float4 l = ((const float4*)(WtLo + k * DOUT))[c4];
        *(float4*)(WsHi + k * LDW + c4 * 4) = h;
        *(float4*)(WsLo + k * LDW + c4 * 4) = l;
    }
    // stage X, splitting to hi/lo tf32
    for (int idx = tid; idx < BM * 32; idx += 256) {
        int r = idx >> 5, c4 = idx & 31;
        int gr = row_base + r;
        float4 v = make_float4(0.f, 0.f, 0.f, 0.f);
        if (gr < nrows) v = ((const float4*)(X + (size_t)gr * DIM))[c4];
        float4 h, l;
        tf32_split(v.x, h.x, l.x);
        tf32_split(v.y, h.y, l.y);
        tf32_split(v.z, h.z, l.z);
        tf32_split(v.w, h.w, l.w);
        *(float4*)(XsHi + r * LDX + c4 * 4) = h;
        *(float4*)(XsLo + r * LDX + c4 * 4) = l;
    }
    __syncthreads();

    int lane = tid & 31, w = tid >> 5;
    int gid = lane >> 2, tig = lane & 3;
    int mg = w & 1, ng = w >> 1;              // 2 m-groups x 4 n-groups
    int n_base = ng * (DOUT / 4);

    const uint32_t* XHi = (const uint32_t*)XsHi;
    const uint32_t* XLo = (const uint32_t*)XsLo;
    const uint32_t* WHi = (const uint32_t*)WsHi;
    const uint32_t* WLo = (const uint32_t*)WsLo;

    float acc[2][NT][4];
    #pragma unroll
    for (int mi = 0; mi < 2; mi++)
        #pragma unroll
        for (int nt = 0; nt < NT; nt++)
            #pragma unroll
            for (int j = 0; j < 4; j++) acc[mi][nt][j] = 0.f;

    #pragma unroll 2
    for (int ks = 0; ks < 16; ks++) {
        int k0 = ks * 8;
        uint32_t ahi[2][4], alo[2][4];
        #pragma unroll
        for (int mi = 0; mi < 2; mi++) {
            int base = (mg * 32 + mi * 16 + gid) * LDX + k0 + tig;
            ahi[mi][0] = XHi[base];
            ahi[mi][1] = XHi[base + 8 * LDX];
            ahi[mi][2] = XHi[base + 4];
            ahi[mi][3] = XHi[base + 8 * LDX + 4];
            alo[mi][0] = XLo[base];
            alo[mi][1] = XLo[base + 8 * LDX];
            alo[mi][2] = XLo[base + 4];
            alo[mi][3] = XLo[base + 8 * LDX + 4];
        }
        #pragma unroll
        for (int nt = 0; nt < NT; nt++) {
            int bb = (k0 + tig) * LDW + n_base + nt * 8 + gid;
            uint32_t bh0 = WHi[bb], bh1 = WHi[bb + 4 * LDW];
            uint32_t bl0 = WLo[bb], bl1 = WLo[bb + 4 * LDW];
            #pragma unroll
            for (int mi = 0; mi < 2; mi++) {
                mma_tf32(acc[mi][nt], ahi[mi], bh0, bh1);   // hi*hi
                mma_tf32(acc[mi][nt], alo[mi], bh0, bh1);   // lo*hi
                mma_tf32(acc[mi][nt], ahi[mi], bl0, bl1);   // hi*lo
            }
        }
    }

    #pragma unroll
    for (int mi = 0; mi < 2; mi++) {
        int r0 = row_base + mg * 32 + mi * 16 + gid;
        #pragma unroll
        for (int nt = 0; nt < NT; nt++) {
            int col = n_base + nt * 8 + tig * 2;
            if (r0 < nrows)
                *(float2*)(g_bufA + (size_t)r0 * DOUT + col) =
                    make_float2(acc[mi][nt][0], acc[mi][nt][1]);
            if (r0 + 8 < nrows)
                *(float2*)(g_bufA + (size_t)(r0 + 8) * DOUT + col) =
                    make_float2(acc[mi][nt][2], acc[mi][nt][3]);
        }
    }
}

// ---------------- propagate (pull/gather via CSR) + bias (+ relu) ----------------
// 4 nodes per block; each thread owns one output feature of one node.
template <int DOUT, bool RELU>
__global__ void prop_kernel(const float* __restrict__ bias, float* __restrict__ out_ext,
                            int dst_ext) {
    const float* Y = g_bufA;
    float* out = dst_ext ? out_ext : g_bufB;
    int node = blockIdx.x * 4 + threadIdx.x / DOUT;
    int col = threadIdx.x % DOUT;
    if (node >= N_NODES) return;
    float di = g_dinv[node];
    float acc = di * di * Y[(size_t)node * DOUT + col];   // self-loop term
    int e = g_offs[node];
    int end = g_offs[node + 1];
    #pragma unroll 4
    for (; e < end; e++) {
        int s = g_src[e];
        acc = fmaf(g_w[e], Y[(size_t)s * DOUT + col], acc);
    }
    acc += bias[col];
    if (RELU) acc = fmaxf(acc, 0.f);
    out[(size_t)node * DOUT + col] = acc;
}

// ---------------- host entry ----------------
extern "C" void kernel_launch(void* const* d_in, const int* in_sizes, int n_in,
                              void* d_out, int out_size) {
    const float* x  = (const float*)d_in[0];
    const void*  ei = d_in[1];
    const float* W0 = (const float*)d_in[2];
    const float* b0 = (const float*)d_in[3];
    const float* W1 = (const float*)d_in[4];
    const float* b1 = (const float*)d_in[5];
    const float* W2 = (const float*)d_in[6];
    const float* b2 = (const float*)d_in[7];
    int E = in_sizes[1] / 2;

    const int SMEM128 = (2 * 64 * 132 + 2 * 128 * 136) * 4;  // 206,848 B
    const int SMEM64  = (2 * 64 * 132 + 2 * 128 * 72) * 4;   // 141,312 B
    cudaFuncSetAttribute(gemm_tf32_kernel<128>, cudaFuncAttributeMaxDynamicSharedMemorySize, SMEM128);
    cudaFuncSetAttribute(gemm_tf32_kernel<64>,  cudaFuncAttributeMaxDynamicSharedMemorySize, SMEM64);

    int nb_nodes = (N_NODES + 255) / 256;
    int nb_edges = (E + 255) / 256;

    // ---- build CSR + normalization + weight prep ----
    zero_detect_kernel<<<nb_nodes, 256>>>((const int*)ei);
    hist_kernel<<<nb_edges, 256>>>(ei, E);
    scan_kernel<<<1, 1024>>>(N_NODES);
    scatter_kernel<<<nb_edges, 256>>>(ei, E);
    prep_weights_kernel<<<(40960 + 255) / 256, 256>>>(W0, W1, W2);

    int gemm_blocks = (N_NODES + 63) / 64;
    int prop_blocks = (N_NODES + 3) / 4;

    // ---- layer 1 ----
    gemm_tf32_kernel<128><<<gemm_blocks, 256, SMEM128>>>(x, 0, 0, N_NODES);
    prop_kernel<128, true><<<prop_blocks, 512>>>(b0, nullptr, 0);
    // ---- layer 2 ----
    gemm_tf32_kernel<128><<<gemm_blocks, 256, SMEM128>>>(nullptr, 1, 1, N_NODES);
    prop_kernel<128, true><<<prop_blocks, 512>>>(b1, nullptr, 0);
    // ---- layer 3 (project 128->64 first, then propagate 64-wide) ----
    gemm_tf32_kernel<64><<<gemm_blocks, 256, SMEM64>>>(nullptr, 1, 2, N_NODES);
    prop_kernel<64, false><<<prop_blocks, 256>>>(b2, (float*)d_out, 1);
}

// round 4
// speedup vs baseline: 1.3971x; 1.3971x over previous
#include <cuda_runtime.h>
#include <math.h>
#include <stdint.h>

#define N_NODES 50000
#define N_EDGES 800000
#define DIM 128

// ---------------- scratch (static device globals; no allocation) ----------------
__device__ int   g_is64;
__device__ int   g_cnt[N_NODES];
__device__ float g_dinv[N_NODES];
__device__ int   g_offs[N_NODES + 1];
__device__ int   g_cursor[N_NODES];
__device__ int   g_src[N_EDGES];
__device__ float g_w[N_EDGES];
__device__ float g_bufA[(size_t)N_NODES * DIM];
__device__ float g_bufB[(size_t)N_NODES * DIM];
__device__ float g_Wt0[DIM * DIM];
__device__ float g_Wt1[DIM * DIM];
__device__ float g_Wt2[DIM * 64];

// ---------------- preprocessing ----------------
// zero counters; block 0 also detects edge-index dtype.
// int64 layout viewed as int32 has all odd words == 0 (node ids < 2^31).
__global__ void zero_detect_kernel(const int* __restrict__ w) {
    int i = blockIdx.x * blockDim.x + threadIdx.x;
    if (i < N_NODES) g_cnt[i] = 0;
    if (blockIdx.x == 0) {
        __shared__ int nz;
        if (threadIdx.x == 0) nz = 0;
        __syncthreads();
        if (w[2 * threadIdx.x + 1] != 0) atomicOr(&nz, 1);
        __syncthreads();
        if (threadIdx.x == 0) g_is64 = (nz == 0) ? 1 : 0;
    }
}

__device__ __forceinline__ int load_idx(const void* ei, int pos) {
    return g_is64 ? (int)((const long long*)ei)[pos] : ((const int*)ei)[pos];
}

// 2 edges per thread: two independent atomic chains -> better latency hiding.
__global__ void hist_kernel(const void* __restrict__ ei, int E) {
    int i = 2 * (blockIdx.x * blockDim.x + threadIdx.x);
    if (i < E) {
        int c = load_idx(ei, E + i);
        if ((unsigned)c < N_NODES) atomicAdd(&g_cnt[c], 1);
    }
    if (i + 1 < E) {
        int c = load_idx(ei, E + i + 1);
        if ((unsigned)c < N_NODES) atomicAdd(&g_cnt[c], 1);
    }
}

// Single-block exclusive scan over g_cnt -> g_offs / g_cursor; also computes dinv.
__global__ void scan_kernel(int n) {
    __shared__ int wsum[32];
    __shared__ int s_carry;
    int tid = threadIdx.x, lane = tid & 31, wid = tid >> 5;
    if (tid == 0) s_carry = 0;
    __syncthreads();
    for (int base = 0; base < n; base += 1024) {
        int i = base + tid;
        int v = (i < n) ? g_cnt[i] : 0;
        if (i < n) g_dinv[i] = rsqrtf((float)(v + 1));   // deg incl. self-loop
        int x = v;
        #pragma unroll
        for (int d = 1; d < 32; d <<= 1) {
            int t = __shfl_up_sync(0xffffffffu, x, d);
            if (lane >= d) x += t;
        }
        if (lane == 31) wsum[wid] = x;
        __syncthreads();
        if (tid < 32) {
            int s = wsum[tid];
            #pragma unroll
            for (int d = 1; d < 32; d <<= 1) {
                int t = __shfl_up_sync(0xffffffffu, s, d);
                if (tid >= d) s += t;
            }
            wsum[tid] = s;
        }
        __syncthreads();
        int carry = s_carry;
        int wpre = (wid == 0) ? 0 : wsum[wid - 1];
        int excl = carry + wpre + (x - v);
        if (i < n) { g_offs[i] = excl; g_cursor[i] = excl; }
        int total = wsum[31];
        __syncthreads();
        if (tid == 0) s_carry = carry + total;
        __syncthreads();
    }
    if (tid == 0) g_offs[n] = s_carry;
}

// 2 edges per thread (two independent atomic+store chains).
__global__ void scatter_kernel(const void* __restrict__ ei, int E) {
    int i = 2 * (blockIdx.x * blockDim.x + threadIdx.x);
    #pragma unroll
    for (int u = 0; u < 2; u++) {
        int j = i + u;
        if (j < E) {
            int r = load_idx(ei, j);
            int c = load_idx(ei, E + j);
            if ((unsigned)r < N_NODES && (unsigned)c < N_NODES) {
                int pos = atomicAdd(&g_cursor[c], 1);
                if ((unsigned)pos < N_EDGES) {
                    g_src[pos] = r;
                    g_w[pos] = g_dinv[r] * g_dinv[c];
                }
            }
        }
    }
}

// Transpose all three weight matrices in one launch. Wt[k][n] = W[n][k].
__global__ void prep_weights_kernel(const float* __restrict__ W0,
                                    const float* __restrict__ W1,
                                    const float* __restrict__ W2) {
    int idx = blockIdx.x * blockDim.x + threadIdx.x;
    const float* W; float* Wt; int dout, off;
    if (idx < 16384)       { W = W0; Wt = g_Wt0; dout = 128; off = idx; }
    else if (idx < 32768)  { W = W1; Wt = g_Wt1; dout = 128; off = idx - 16384; }
    else if (idx < 40960)  { W = W2; Wt = g_Wt2; dout = 64;  off = idx - 32768; }
    else return;
    int n = off / 128, k = off % 128;   // W is [dout][128]
    Wt[k * dout + n] = W[off];
}

// ---------------- fp32 GEMM: g_bufA[N,DOUT] = X[N,128] @ Wt ([128][DOUT]) ----------------
// src_global: X = g_bufB; else X = Xext. wsel picks weight global.
template <int DOUT>
__global__ void gemm_kernel(const float* __restrict__ Xext, int src_global, int wsel,
                            int nrows) {
    constexpr int BM = 64;
    constexpr int TN = 4;
    constexpr int NCG = DOUT / TN;                 // 32 or 16 col-groups
    constexpr int TM = (BM * DOUT) / (256 * TN);   // 8 or 4 rows per thread
    const float* X = src_global ? g_bufB : Xext;
    const float* Wt = (wsel == 0) ? g_Wt0 : (wsel == 1) ? g_Wt1 : g_Wt2;
    float* Y = g_bufA;
    extern __shared__ float smem[];
    float* Xs = smem;                  // [BM][128]
    float* Ws = smem + BM * DIM;       // [128][DOUT]
    int tid = threadIdx.x;
    int row_base = blockIdx.x * BM;

    for (int idx = tid; idx < DIM * DOUT / 4; idx += 256)
        ((float4*)Ws)[idx] = ((const float4*)Wt)[idx];
    for (int idx = tid; idx < BM * DIM / 4; idx += 256) {
        int r = idx >> 5;
        int c4 = idx & 31;
        float4 v = make_float4(0.f, 0.f, 0.f, 0.f);
        int gr = row_base + r;
        if (gr < nrows) v = ((const float4*)(X + (size_t)gr * DIM))[c4];
        ((float4*)(Xs + r * DIM))[c4] = v;
    }
    __syncthreads();

    int cg = tid % NCG, rg = tid / NCG;
    int col0 = cg * TN, row0 = rg * TM;
    float acc[TM][TN];
    #pragma unroll
    for (int m = 0; m < TM; m++)
        #pragma unroll
        for (int n = 0; n < TN; n++) acc[m][n] = 0.f;

    #pragma unroll 2
    for (int k4 = 0; k4 < DIM / 4; k4++) {
        float4 av[TM];
        #pragma unroll
        for (int m = 0; m < TM; m++)
            av[m] = *(const float4*)(Xs + (row0 + m) * DIM + k4 * 4);
        #pragma unroll
        for (int kk = 0; kk < 4; kk++) {
            float4 bv = *(const float4*)(Ws + (k4 * 4 + kk) * DOUT + col0);
            #pragma unroll
            for (int m = 0; m < TM; m++) {
                float a = (kk == 0) ? av[m].x : (kk == 1) ? av[m].y : (kk == 2) ? av[m].z : av[m].w;
                acc[m][0] = fmaf(a, bv.x, acc[m][0]);
                acc[m][1] = fmaf(a, bv.y, acc[m][1]);
                acc[m][2] = fmaf(a, bv.z, acc[m][2]);
                acc[m][3] = fmaf(a, bv.w, acc[m][3]);
            }
        }
    }

    #pragma unroll
    for (int m = 0; m < TM; m++) {
        int gr = row_base + row0 + m;
        if (gr < nrows)
            *(float4*)(Y + (size_t)gr * DOUT + col0) =
                make_float4(acc[m][0], acc[m][1], acc[m][2], acc[m][3]);
    }
}

// ---------------- propagate (pull/gather via CSR) + bias (+ relu) ----------------
// Vectorized: C4 = DOUT/4 threads per node, each thread owns a float4 of columns.
// One edge = one warp-coalesced 128B-per-8-lane read (LDG.128).
template <int DOUT, bool RELU>
__global__ void prop_kernel(const float* __restrict__ bias, float* __restrict__ out_ext,
                            int dst_ext) {
    constexpr int C4 = DOUT / 4;                 // 32 (DOUT=128) or 16 (DOUT=64)
    constexpr int NPB = 256 / C4;                // nodes per 256-thread block
    const float4* Y4 = (const float4*)g_bufA;
    float4* out4 = dst_ext ? (float4*)out_ext : (float4*)g_bufB;
    int tin = threadIdx.x % C4;
    int node = blockIdx.x * NPB + threadIdx.x / C4;
    if (node >= N_NODES) return;

    float di = g_dinv[node];
    float self_w = di * di;
    float4 v = Y4[(size_t)node * C4 + tin];
    float4 acc;
    acc.x = self_w * v.x; acc.y = self_w * v.y;
    acc.z = self_w * v.z; acc.w = self_w * v.w;

    int e = g_offs[node];
    int end = g_offs[node + 1];
    // unroll 2: two independent load+fma chains in flight
    for (; e + 1 < end; e += 2) {
        float w0 = g_w[e],     w1 = g_w[e + 1];
        int   s0 = g_src[e],   s1 = g_src[e + 1];
        float4 v0 = Y4[(size_t)s0 * C4 + tin];
        float4 v1 = Y4[(size_t)s1 * C4 + tin];
        acc.x = fmaf(w0, v0.x, acc.x); acc.y = fmaf(w0, v0.y, acc.y);
        acc.z = fmaf(w0, v0.z, acc.z); acc.w = fmaf(w0, v0.w, acc.w);
        acc.x = fmaf(w1, v1.x, acc.x); acc.y = fmaf(w1, v1.y, acc.y);
        acc.z = fmaf(w1, v1.z, acc.z); acc.w = fmaf(w1, v1.w, acc.w);
    }
    if (e < end) {
        float w0 = g_w[e];
        float4 v0 = Y4[(size_t)g_src[e] * C4 + tin];
        acc.x = fmaf(w0, v0.x, acc.x); acc.y = fmaf(w0, v0.y, acc.y);
        acc.z = fmaf(w0, v0.z, acc.z); acc.w = fmaf(w0, v0.w, acc.w);
    }

    float4 b = ((const float4*)bias)[tin];
    acc.x += b.x; acc.y += b.y; acc.z += b.z; acc.w += b.w;
    if (RELU) {
        acc.x = fmaxf(acc.x, 0.f); acc.y = fmaxf(acc.y, 0.f);
        acc.z = fmaxf(acc.z, 0.f); acc.w = fmaxf(acc.w, 0.f);
    }
    out4[(size_t)node * C4 + tin] = acc;
}

// ---------------- host entry ----------------
extern "C" void kernel_launch(void* const* d_in, const int* in_sizes, int n_in,
                              void* d_out, int out_size) {
    const float* x  = (const float*)d_in[0];
    const void*  ei = d_in[1];
    const float* W0 = (const float*)d_in[2];
    const float* b0 = (const float*)d_in[3];
    const float* W1 = (const float*)d_in[4];
    const float* b1 = (const float*)d_in[5];
    const float* W2 = (const float*)d_in[6];
    const float* b2 = (const float*)d_in[7];
    int E = in_sizes[1] / 2;

    const int SMEM128 = (64 * DIM + DIM * 128) * 4;  // 96 KB -> 2 CTA/SM
    const int SMEM64  = (64 * DIM + DIM * 64) * 4;   // 64 KB
    cudaFuncSetAttribute(gemm_kernel<128>, cudaFuncAttributeMaxDynamicSharedMemorySize, SMEM128);
    cudaFuncSetAttribute(gemm_kernel<64>,  cudaFuncAttributeMaxDynamicSharedMemorySize, SMEM64);

    int nb_nodes = (N_NODES + 255) / 256;
    int nb_edges2 = (E / 2 + 255) / 256;

    // ---- build CSR + normalization + weight prep ----
    zero_detect_kernel<<<nb_nodes, 256>>>((const int*)ei);
    hist_kernel<<<nb_edges2, 256>>>(ei, E);
    scan_kernel<<<1, 1024>>>(N_NODES);
    scatter_kernel<<<nb_edges2, 256>>>(ei, E);
    prep_weights_kernel<<<(40960 + 255) / 256, 256>>>(W0, W1, W2);

    int gemm_blocks = (N_NODES + 63) / 64;
    int prop_blocks128 = (N_NODES + 7) / 8;    // 8 nodes/block (C4=32)
    int prop_blocks64  = (N_NODES + 15) / 16;  // 16 nodes/block (C4=16)

    // ---- layer 1 ----
    gemm_kernel<128><<<gemm_blocks, 256, SMEM128>>>(x, 0, 0, N_NODES);
    prop_kernel<128, true><<<prop_blocks128, 256>>>(b0, nullptr, 0);
    // ---- layer 2 ----
    gemm_kernel<128><<<gemm_blocks, 256, SMEM128>>>(nullptr, 1, 1, N_NODES);
    prop_kernel<128, true><<<prop_blocks128, 256>>>(b1, nullptr, 0);
    // ---- layer 3 (project 128->64 first, then propagate 64-wide) ----
    gemm_kernel<64><<<gemm_blocks, 256, SMEM64>>>(nullptr, 1, 2, N_NODES);
    prop_kernel<64, false><<<prop_blocks64, 256>>>(b2, (float*)d_out, 1);
}